// round 1
// baseline (speedup 1.0000x reference)
#include <cuda_runtime.h>
#include <cuda_bf16.h>
#include <cstdint>

// Problem constants
#define BB 32
#define LL 4096
#define DD 512
#define MODES 64
#define NK 128          // 2*MODES (real rows + imag rows)

// ---------------------------------------------------------------------------
// Static device scratch (allocation-free rule: __device__ globals only)
// ---------------------------------------------------------------------------
__device__ float g_S1A[NK * LL];                 // [128][4096]  rows<64: cos, rows>=64: -sin   (2 MB)
__device__ float g_S3A[LL * NK];                 // [4096][128]  [l][k]: k<64 cos, k>=64 -sin   (2 MB)
__device__ float g_Wt[2ull * MODES * DD * DD];   // [ri][m][d][e]                              (134 MB)
__device__ float g_Q[BB * NK * DD];              // [b][row][d]  row<64: Qr(m), row>=64: Qi(m) (8.4 MB)
__device__ float g_Am[BB * NK * DD];             // [b][k][e]    scaled spectral coeffs        (8.4 MB)

// ---------------------------------------------------------------------------
// Init: twiddle tables.  theta = 2*pi*m*l/L ; integer reduction r=(m*l)&4095
// ---------------------------------------------------------------------------
__global__ void fno_init_tables() {
    int idx = blockIdx.x * blockDim.x + threadIdx.x;   // over 128*4096
    if (idx >= NK * LL) return;
    int row = idx >> 12;          // 0..127
    int l   = idx & (LL - 1);     // 0..4095
    int m   = row & (MODES - 1);
    int r   = (m * l) & (LL - 1); // exact phase index
    float s, c;
    sincospif((float)r * (1.0f / 2048.0f), &s, &c);    // sin/cos(2*pi*r/4096)
    float v = (row < MODES) ? c : -s;
    g_S1A[row * LL + l] = v;
    g_S3A[l * NK + row] = v;
}

// ---------------------------------------------------------------------------
// Weight transpose:  Wt[ri][m][d][e] = w_ri[d][e][m]
// grid: (e_tile=16, m_tile=2, d=512), block (32,8)
// ---------------------------------------------------------------------------
__global__ void fno_transpose_w(const float* __restrict__ wr,
                                const float* __restrict__ wi) {
    __shared__ float t[2][32][33];
    int d  = blockIdx.z;
    int e0 = blockIdx.x * 32;
    int m0 = blockIdx.y * 32;
    int tx = threadIdx.x, ty = threadIdx.y;
    size_t src_base = ((size_t)d * DD) * MODES + m0;   // + e*MODES + tx
    for (int i = ty; i < 32; i += 8) {
        t[0][i][tx] = wr[src_base + (size_t)(e0 + i) * MODES + tx];
        t[1][i][tx] = wi[src_base + (size_t)(e0 + i) * MODES + tx];
    }
    __syncthreads();
    for (int i = ty; i < 32; i += 8) {
        size_t dst0 = (((size_t)(m0 + i)) * DD + d) * DD + e0 + tx;
        g_Wt[dst0]                              = t[0][tx][i];
        g_Wt[dst0 + (size_t)MODES * DD * DD]    = t[1][tx][i];
    }
}

// ---------------------------------------------------------------------------
// Stage 1: per-batch GEMM  C[128,512] = S1A[128,4096] x q_b[4096,512]
// grid: (ntile=8, b=32), block 256.  Tile BM=128, BN=64, BK=16, thread 8x4.
// ---------------------------------------------------------------------------
__global__ __launch_bounds__(256) void fno_stage1(const float* __restrict__ q) {
    __shared__ float As[16][128];
    __shared__ float Bs[16][68];            // pad to 68 (16B-aligned rows)
    const int b  = blockIdx.y;
    const int n0 = blockIdx.x * 64;
    const float* qb = q + (size_t)b * LL * DD;
    const int tid = threadIdx.x;
    const int tx = tid & 15;                // -> n group (4 cols)
    const int ty = tid >> 4;                // -> m group (8 rows)

    float acc[8][4];
#pragma unroll
    for (int i = 0; i < 8; i++)
#pragma unroll
        for (int j = 0; j < 4; j++) acc[i][j] = 0.0f;

    for (int k0 = 0; k0 < LL; k0 += 16) {
        // A tile: 128 rows x 16 k  (512 float4, 2 per thread), transposed store
#pragma unroll
        for (int i = 0; i < 2; i++) {
            int t   = tid + i * 256;
            int row = t >> 2;
            int q4  = t & 3;
            float4 v = *(const float4*)&g_S1A[row * LL + k0 + q4 * 4];
            As[q4 * 4 + 0][row] = v.x;
            As[q4 * 4 + 1][row] = v.y;
            As[q4 * 4 + 2][row] = v.z;
            As[q4 * 4 + 3][row] = v.w;
        }
        // B tile: 16 rows x 64 cols (1 float4 per thread)
        {
            int row = tid >> 4;
            int c4  = tid & 15;
            float4 v = *(const float4*)&qb[(size_t)(k0 + row) * DD + n0 + c4 * 4];
            *(float4*)&Bs[row][c4 * 4] = v;
        }
        __syncthreads();
#pragma unroll
        for (int kk = 0; kk < 16; kk++) {
            float a[8], bv[4];
            *(float4*)&a[0] = *(float4*)&As[kk][ty * 8];
            *(float4*)&a[4] = *(float4*)&As[kk][ty * 8 + 4];
            *(float4*)&bv[0] = *(float4*)&Bs[kk][tx * 4];
#pragma unroll
            for (int i = 0; i < 8; i++)
#pragma unroll
                for (int j = 0; j < 4; j++) acc[i][j] += a[i] * bv[j];
        }
        __syncthreads();
    }
#pragma unroll
    for (int i = 0; i < 8; i++) {
        int row = ty * 8 + i;
#pragma unroll
        for (int j = 0; j < 4; j++)
            g_Q[((size_t)b * NK + row) * DD + n0 + tx * 4 + j] = acc[i][j];
    }
}

// ---------------------------------------------------------------------------
// Stage 2: per-mode complex GEMM.
//   Or[b,e] = sum_d Qr*Wr - Qi*Wi ;  Oi[b,e] = sum_d Qr*Wi + Qi*Wr
// grid: (etile=4, mode=64), block 256. Output tile 32(b) x 128(e), thread 2x8.
// ---------------------------------------------------------------------------
__global__ __launch_bounds__(256) void fno_stage2() {
    __shared__ float Qs[2][16][32];     // [ri][k][b]
    __shared__ float Ws[2][16][128];    // [ri][k][e]
    const int m  = blockIdx.y;
    const int e0 = blockIdx.x * 128;
    const int tid = threadIdx.x;
    const int tx = tid & 15;            // e group of 8
    const int ty = tid >> 4;            // b pair

    float accr[2][8], acci[2][8];
#pragma unroll
    for (int i = 0; i < 2; i++)
#pragma unroll
        for (int j = 0; j < 8; j++) { accr[i][j] = 0.0f; acci[i][j] = 0.0f; }

    for (int d0 = 0; d0 < DD; d0 += 16) {
        // Q tile: 2 ri x 32 b x 16 d  (256 float4, 1 per thread), transposed store
        {
            int ri = tid >> 7;
            int t  = tid & 127;
            int bb = t >> 2;
            int q4 = t & 3;
            float4 v = *(const float4*)&g_Q[((size_t)bb * NK + ri * MODES + m) * DD + d0 + q4 * 4];
            Qs[ri][q4 * 4 + 0][bb] = v.x;
            Qs[ri][q4 * 4 + 1][bb] = v.y;
            Qs[ri][q4 * 4 + 2][bb] = v.z;
            Qs[ri][q4 * 4 + 3][bb] = v.w;
        }
        // W tile: 2 ri x 16 d x 128 e (1024 float4, 4 per thread)
#pragma unroll
        for (int i = 0; i < 4; i++) {
            int t  = tid + i * 256;
            int ri = t >> 9;
            int r  = t & 511;
            int kk = r >> 5;
            int c4 = r & 31;
            float4 v = *(const float4*)&g_Wt[(((size_t)ri * MODES + m) * DD + d0 + kk) * DD + e0 + c4 * 4];
            *(float4*)&Ws[ri][kk][c4 * 4] = v;
        }
        __syncthreads();
#pragma unroll
        for (int kk = 0; kk < 16; kk++) {
            float qr[2], qi[2], wrv[8], wiv[8];
            qr[0] = Qs[0][kk][ty * 2];
            qr[1] = Qs[0][kk][ty * 2 + 1];
            qi[0] = Qs[1][kk][ty * 2];
            qi[1] = Qs[1][kk][ty * 2 + 1];
            *(float4*)&wrv[0] = *(float4*)&Ws[0][kk][tx * 8];
            *(float4*)&wrv[4] = *(float4*)&Ws[0][kk][tx * 8 + 4];
            *(float4*)&wiv[0] = *(float4*)&Ws[1][kk][tx * 8];
            *(float4*)&wiv[4] = *(float4*)&Ws[1][kk][tx * 8 + 4];
#pragma unroll
            for (int i = 0; i < 2; i++)
#pragma unroll
                for (int j = 0; j < 8; j++) {
                    accr[i][j] += qr[i] * wrv[j];
                    accr[i][j] -= qi[i] * wiv[j];
                    acci[i][j] += qr[i] * wiv[j];
                    acci[i][j] += qi[i] * wrv[j];
                }
        }
        __syncthreads();
    }
    const float cscale = (m == 0) ? (1.0f / (float)LL) : (2.0f / (float)LL);
#pragma unroll
    for (int i = 0; i < 2; i++) {
        int bb = ty * 2 + i;
#pragma unroll
        for (int j = 0; j < 8; j++) {
            int e = e0 + tx * 8 + j;
            g_Am[((size_t)bb * NK + m) * DD + e]         = cscale * accr[i][j];
            g_Am[((size_t)bb * NK + MODES + m) * DD + e] = cscale * acci[i][j];
        }
    }
}

// ---------------------------------------------------------------------------
// Stage 3: per-batch GEMM  out_b[4096,512] = S3A[4096,128] x Am_b[128,512]
// grid: (ntile=8, mtile=32, b=32), block 256. BM=128, BN=64, BK=16, thread 8x4.
// ---------------------------------------------------------------------------
__global__ __launch_bounds__(256) void fno_stage3(float* __restrict__ out) {
    __shared__ float As[16][128];
    __shared__ float Bs[16][68];
    const int b  = blockIdx.z;
    const int m0 = blockIdx.y * 128;
    const int n0 = blockIdx.x * 64;
    const int tid = threadIdx.x;
    const int tx = tid & 15;
    const int ty = tid >> 4;

    float acc[8][4];
#pragma unroll
    for (int i = 0; i < 8; i++)
#pragma unroll
        for (int j = 0; j < 4; j++) acc[i][j] = 0.0f;

    for (int k0 = 0; k0 < NK; k0 += 16) {
        // A tile: rows m0..m0+127, 16 k
#pragma unroll
        for (int i = 0; i < 2; i++) {
            int t   = tid + i * 256;
            int row = t >> 2;
            int q4  = t & 3;
            float4 v = *(const float4*)&g_S3A[(size_t)(m0 + row) * NK + k0 + q4 * 4];
            As[q4 * 4 + 0][row] = v.x;
            As[q4 * 4 + 1][row] = v.y;
            As[q4 * 4 + 2][row] = v.z;
            As[q4 * 4 + 3][row] = v.w;
        }
        // B tile: Am[b][k0+row][n0..n0+63]
        {
            int row = tid >> 4;
            int c4  = tid & 15;
            float4 v = *(const float4*)&g_Am[((size_t)b * NK + k0 + row) * DD + n0 + c4 * 4];
            *(float4*)&Bs[row][c4 * 4] = v;
        }
        __syncthreads();
#pragma unroll
        for (int kk = 0; kk < 16; kk++) {
            float a[8], bv[4];
            *(float4*)&a[0] = *(float4*)&As[kk][ty * 8];
            *(float4*)&a[4] = *(float4*)&As[kk][ty * 8 + 4];
            *(float4*)&bv[0] = *(float4*)&Bs[kk][tx * 4];
#pragma unroll
            for (int i = 0; i < 8; i++)
#pragma unroll
                for (int j = 0; j < 4; j++) acc[i][j] += a[i] * bv[j];
        }
        __syncthreads();
    }
#pragma unroll
    for (int i = 0; i < 8; i++) {
        int l = m0 + ty * 8 + i;
#pragma unroll
        for (int j = 0; j < 4; j++)
            out[((size_t)b * LL + l) * DD + n0 + tx * 4 + j] = acc[i][j];
    }
}

// ---------------------------------------------------------------------------
// Launch
// ---------------------------------------------------------------------------
extern "C" void kernel_launch(void* const* d_in, const int* in_sizes, int n_in,
                              void* d_out, int out_size) {
    (void)in_sizes; (void)n_in; (void)out_size;
    const float* q  = (const float*)d_in[0];
    const float* wr = (const float*)d_in[1];
    const float* wi = (const float*)d_in[2];
    float* out = (float*)d_out;

    fno_init_tables<<<(NK * LL + 255) / 256, 256>>>();
    fno_transpose_w<<<dim3(16, 2, 512), dim3(32, 8)>>>(wr, wi);
    fno_stage1<<<dim3(8, 32), 256>>>(q);
    fno_stage2<<<dim3(4, 64), 256>>>();
    fno_stage3<<<dim3(8, 32, 32), 256>>>(out);
}

// round 2
// speedup vs baseline: 2.2259x; 2.2259x over previous
#include <cuda_runtime.h>
#include <cuda_bf16.h>
#include <cstdint>

// Problem constants
#define BB 32
#define LL 4096
#define DD 512
#define MODES 64
#define NK 128          // 2*MODES (real rows + imag rows)

// ---------------------------------------------------------------------------
// Static device scratch
// ---------------------------------------------------------------------------
__device__ float g_S1A[NK * LL];                 // [128][4096] rows<64: cos, >=64: -sin (tf32-rounded)
__device__ float g_S3A[LL * NK];                 // [4096][128] (tf32-rounded)
__device__ float g_Wt[2ull * MODES * DD * DD];   // [ri][m][d][e]
__device__ float g_Q[BB * NK * DD];              // [b][row][d]
__device__ float g_Am[BB * NK * DD];             // [b][k][e] (tf32-rounded)

// ---------------------------------------------------------------------------
// Helpers
// ---------------------------------------------------------------------------
__device__ __forceinline__ uint32_t f2tf(float f) {
    uint32_t u;
    asm("cvt.rna.tf32.f32 %0, %1;" : "=r"(u) : "f"(f));
    return u;
}

__device__ __forceinline__ void mma_tf32(float c[4],
                                         uint32_t a0, uint32_t a1, uint32_t a2, uint32_t a3,
                                         uint32_t b0, uint32_t b1) {
    asm volatile(
        "mma.sync.aligned.m16n8k8.row.col.f32.tf32.tf32.f32 "
        "{%0,%1,%2,%3}, {%4,%5,%6,%7}, {%8,%9}, {%0,%1,%2,%3};"
        : "+f"(c[0]), "+f"(c[1]), "+f"(c[2]), "+f"(c[3])
        : "r"(a0), "r"(a1), "r"(a2), "r"(a3), "r"(b0), "r"(b1));
}

__device__ __forceinline__ void cp16(uint32_t dst_smem, const void* src) {
    asm volatile("cp.async.cg.shared.global [%0], [%1], 16;" :: "r"(dst_smem), "l"(src));
}
__device__ __forceinline__ void cp_commit() { asm volatile("cp.async.commit_group;"); }

// ---------------------------------------------------------------------------
// Init: twiddle tables, rounded to tf32 (rna) so MMA consumes them directly.
// ---------------------------------------------------------------------------
__global__ void fno_init_tables() {
    int idx = blockIdx.x * blockDim.x + threadIdx.x;
    if (idx >= NK * LL) return;
    int row = idx >> 12;
    int l   = idx & (LL - 1);
    int m   = row & (MODES - 1);
    int r   = (m * l) & (LL - 1);
    float s, c;
    sincospif((float)r * (1.0f / 2048.0f), &s, &c);
    float v = (row < MODES) ? c : -s;
    float vt = __uint_as_float(f2tf(v));
    g_S1A[row * LL + l] = vt;
    g_S3A[l * NK + row] = vt;
}

// ---------------------------------------------------------------------------
// Weight transpose:  Wt[ri][m][d][e] = w_ri[d][e][m]
// ---------------------------------------------------------------------------
__global__ void fno_transpose_w(const float* __restrict__ wr,
                                const float* __restrict__ wi) {
    __shared__ float t[2][32][33];
    int d  = blockIdx.z;
    int e0 = blockIdx.x * 32;
    int m0 = blockIdx.y * 32;
    int tx = threadIdx.x, ty = threadIdx.y;
    size_t src_base = ((size_t)d * DD) * MODES + m0;
    for (int i = ty; i < 32; i += 8) {
        t[0][i][tx] = wr[src_base + (size_t)(e0 + i) * MODES + tx];
        t[1][i][tx] = wi[src_base + (size_t)(e0 + i) * MODES + tx];
    }
    __syncthreads();
    for (int i = ty; i < 32; i += 8) {
        size_t dst0 = (((size_t)(m0 + i)) * DD + d) * DD + e0 + tx;
        g_Wt[dst0]                           = t[0][tx][i];
        g_Wt[dst0 + (size_t)MODES * DD * DD] = t[1][tx][i];
    }
}

// ---------------------------------------------------------------------------
// Stage 1 (tf32 MMA): per-batch C[128,512] = S1A[128,4096] x q_b[4096,512]
// grid (4,32), block 256. BM=128 BN=128 BK=32, warps 2x4, warp tile 64x32.
// ---------------------------------------------------------------------------
#define S1_ASZ (128 * 36)
#define S1_BSZ (32 * 136)
#define S1_BUF (S1_ASZ + S1_BSZ)
#define S1_SMEM (2 * S1_BUF * 4)

__global__ __launch_bounds__(256) void fno_stage1_mma(const float* __restrict__ q) {
    extern __shared__ float sm[];
    const int b  = blockIdx.y;
    const int n0 = blockIdx.x * 128;
    const float* qb = q + (size_t)b * LL * DD;
    const int tid = threadIdx.x;
    const int warp = tid >> 5, lane = tid & 31;
    const int wm = warp >> 2, wn = warp & 3;
    const int gid = lane >> 2, tig = lane & 3;
    const uint32_t smem_u = (uint32_t)__cvta_generic_to_shared(sm);

    float acc[4][4][4];
#pragma unroll
    for (int i = 0; i < 4; i++)
#pragma unroll
        for (int j = 0; j < 4; j++)
#pragma unroll
            for (int k = 0; k < 4; k++) acc[i][j][k] = 0.0f;

    // ---- async tile loader ----
    auto load_tiles = [&](int buf, int k0) {
        uint32_t aB = smem_u + buf * S1_BUF * 4;
        uint32_t bB = aB + S1_ASZ * 4;
#pragma unroll
        for (int i = 0; i < 4; i++) {
            int idx = tid + i * 256;            // 1024 float4 of A
            int row = idx >> 3, c4 = idx & 7;
            cp16(aB + (row * 36 + c4 * 4) * 4, &g_S1A[row * LL + k0 + c4 * 4]);
        }
#pragma unroll
        for (int i = 0; i < 4; i++) {
            int idx = tid + i * 256;            // 1024 float4 of B
            int kr = idx >> 5, c4 = idx & 31;
            cp16(bB + (kr * 136 + c4 * 4) * 4, &qb[(size_t)(k0 + kr) * DD + n0 + c4 * 4]);
        }
        cp_commit();
    };

    load_tiles(0, 0);
    int buf = 0;
    const int NT = LL / 32;
    for (int kt = 0; kt < NT; kt++) {
        if (kt + 1 < NT) {
            load_tiles(buf ^ 1, (kt + 1) * 32);
            asm volatile("cp.async.wait_group 1;");
        } else {
            asm volatile("cp.async.wait_group 0;");
        }
        __syncthreads();
        const float* As = sm + buf * S1_BUF;
        const float* Bs = As + S1_ASZ;
#pragma unroll
        for (int ks = 0; ks < 4; ks++) {
            uint32_t a[4][4];
#pragma unroll
            for (int tm = 0; tm < 4; tm++) {
                const float* ap = As + (wm * 64 + tm * 16 + gid) * 36 + ks * 8 + tig;
                a[tm][0] = __float_as_uint(ap[0]);
                a[tm][1] = __float_as_uint(ap[8 * 36]);
                a[tm][2] = __float_as_uint(ap[4]);
                a[tm][3] = __float_as_uint(ap[8 * 36 + 4]);
            }
            uint32_t bf[4][2];
#pragma unroll
            for (int tn = 0; tn < 4; tn++) {
                const float* bp = Bs + (ks * 8 + tig) * 136 + wn * 32 + tn * 8 + gid;
                bf[tn][0] = f2tf(bp[0]);
                bf[tn][1] = f2tf(bp[4 * 136]);
            }
#pragma unroll
            for (int tm = 0; tm < 4; tm++)
#pragma unroll
                for (int tn = 0; tn < 4; tn++)
                    mma_tf32(acc[tm][tn], a[tm][0], a[tm][1], a[tm][2], a[tm][3],
                             bf[tn][0], bf[tn][1]);
        }
        __syncthreads();
        buf ^= 1;
    }

    // epilogue -> g_Q[b][row][col]
#pragma unroll
    for (int tm = 0; tm < 4; tm++) {
        int r = wm * 64 + tm * 16 + gid;
#pragma unroll
        for (int tn = 0; tn < 4; tn++) {
            int c = n0 + wn * 32 + tn * 8 + tig * 2;
            float2 v0 = make_float2(acc[tm][tn][0], acc[tm][tn][1]);
            float2 v1 = make_float2(acc[tm][tn][2], acc[tm][tn][3]);
            *(float2*)&g_Q[((size_t)b * NK + r) * DD + c]     = v0;
            *(float2*)&g_Q[((size_t)b * NK + r + 8) * DD + c] = v1;
        }
    }
}

// ---------------------------------------------------------------------------
// Stage 2 (FFMA, unchanged math): per-mode complex GEMM. Output tf32-rounded.
// ---------------------------------------------------------------------------
__global__ __launch_bounds__(256) void fno_stage2() {
    __shared__ float Qs[2][16][32];
    __shared__ float Ws[2][16][128];
    const int m  = blockIdx.y;
    const int e0 = blockIdx.x * 128;
    const int tid = threadIdx.x;
    const int tx = tid & 15;
    const int ty = tid >> 4;

    float accr[2][8], acci[2][8];
#pragma unroll
    for (int i = 0; i < 2; i++)
#pragma unroll
        for (int j = 0; j < 8; j++) { accr[i][j] = 0.0f; acci[i][j] = 0.0f; }

    for (int d0 = 0; d0 < DD; d0 += 16) {
        {
            int ri = tid >> 7;
            int t  = tid & 127;
            int bb = t >> 2;
            int q4 = t & 3;
            float4 v = *(const float4*)&g_Q[((size_t)bb * NK + ri * MODES + m) * DD + d0 + q4 * 4];
            Qs[ri][q4 * 4 + 0][bb] = v.x;
            Qs[ri][q4 * 4 + 1][bb] = v.y;
            Qs[ri][q4 * 4 + 2][bb] = v.z;
            Qs[ri][q4 * 4 + 3][bb] = v.w;
        }
#pragma unroll
        for (int i = 0; i < 4; i++) {
            int t  = tid + i * 256;
            int ri = t >> 9;
            int r  = t & 511;
            int kk = r >> 5;
            int c4 = r & 31;
            float4 v = *(const float4*)&g_Wt[(((size_t)ri * MODES + m) * DD + d0 + kk) * DD + e0 + c4 * 4];
            *(float4*)&Ws[ri][kk][c4 * 4] = v;
        }
        __syncthreads();
#pragma unroll
        for (int kk = 0; kk < 16; kk++) {
            float qr[2], qi[2], wrv[8], wiv[8];
            qr[0] = Qs[0][kk][ty * 2];
            qr[1] = Qs[0][kk][ty * 2 + 1];
            qi[0] = Qs[1][kk][ty * 2];
            qi[1] = Qs[1][kk][ty * 2 + 1];
            *(float4*)&wrv[0] = *(float4*)&Ws[0][kk][tx * 8];
            *(float4*)&wrv[4] = *(float4*)&Ws[0][kk][tx * 8 + 4];
            *(float4*)&wiv[0] = *(float4*)&Ws[1][kk][tx * 8];
            *(float4*)&wiv[4] = *(float4*)&Ws[1][kk][tx * 8 + 4];
#pragma unroll
            for (int i = 0; i < 2; i++)
#pragma unroll
                for (int j = 0; j < 8; j++) {
                    accr[i][j] += qr[i] * wrv[j];
                    accr[i][j] -= qi[i] * wiv[j];
                    acci[i][j] += qr[i] * wiv[j];
                    acci[i][j] += qi[i] * wrv[j];
                }
        }
        __syncthreads();
    }
    const float cscale = (m == 0) ? (1.0f / (float)LL) : (2.0f / (float)LL);
#pragma unroll
    for (int i = 0; i < 2; i++) {
        int bb = ty * 2 + i;
#pragma unroll
        for (int j = 0; j < 8; j++) {
            int e = e0 + tx * 8 + j;
            g_Am[((size_t)bb * NK + m) * DD + e] =
                __uint_as_float(f2tf(cscale * accr[i][j]));
            g_Am[((size_t)bb * NK + MODES + m) * DD + e] =
                __uint_as_float(f2tf(cscale * acci[i][j]));
        }
    }
}

// ---------------------------------------------------------------------------
// Stage 3 (tf32 MMA): out_b[4096,512] = S3A[4096,128] x Am_b[128,512]
// grid (4,32,32), block 256. BM=128 BN=128 K=128 single-shot smem.
// ---------------------------------------------------------------------------
#define S3_ASZ (128 * 132)
#define S3_BSZ (128 * 136)
#define S3_SMEM ((S3_ASZ + S3_BSZ) * 4)

__global__ __launch_bounds__(256) void fno_stage3_mma(float* __restrict__ out) {
    extern __shared__ float sm[];
    const int b  = blockIdx.z;
    const int m0 = blockIdx.y * 128;
    const int n0 = blockIdx.x * 128;
    const int tid = threadIdx.x;
    const int warp = tid >> 5, lane = tid & 31;
    const int wm = warp >> 2, wn = warp & 3;
    const int gid = lane >> 2, tig = lane & 3;
    const uint32_t smem_u = (uint32_t)__cvta_generic_to_shared(sm);
    const float* As = sm;
    const float* Bs = sm + S3_ASZ;

    // load A [128][128] and B [128][128] fully
    {
        uint32_t aB = smem_u;
        uint32_t bB = smem_u + S3_ASZ * 4;
#pragma unroll
        for (int i = 0; i < 16; i++) {
            int idx = tid + i * 256;
            int row = idx >> 5, c4 = idx & 31;
            cp16(aB + (row * 132 + c4 * 4) * 4, &g_S3A[(size_t)(m0 + row) * NK + c4 * 4]);
        }
#pragma unroll
        for (int i = 0; i < 16; i++) {
            int idx = tid + i * 256;
            int row = idx >> 5, c4 = idx & 31;
            cp16(bB + (row * 136 + c4 * 4) * 4, &g_Am[((size_t)b * NK + row) * DD + n0 + c4 * 4]);
        }
        cp_commit();
        asm volatile("cp.async.wait_group 0;");
        __syncthreads();
    }

    float acc[4][4][4];
#pragma unroll
    for (int i = 0; i < 4; i++)
#pragma unroll
        for (int j = 0; j < 4; j++)
#pragma unroll
            for (int k = 0; k < 4; k++) acc[i][j][k] = 0.0f;

#pragma unroll 4
    for (int ks = 0; ks < 16; ks++) {
        uint32_t a[4][4];
#pragma unroll
        for (int tm = 0; tm < 4; tm++) {
            const float* ap = As + (wm * 64 + tm * 16 + gid) * 132 + ks * 8 + tig;
            a[tm][0] = __float_as_uint(ap[0]);
            a[tm][1] = __float_as_uint(ap[8 * 132]);
            a[tm][2] = __float_as_uint(ap[4]);
            a[tm][3] = __float_as_uint(ap[8 * 132 + 4]);
        }
        uint32_t bf[4][2];
#pragma unroll
        for (int tn = 0; tn < 4; tn++) {
            const float* bp = Bs + (ks * 8 + tig) * 136 + wn * 32 + tn * 8 + gid;
            bf[tn][0] = __float_as_uint(bp[0]);
            bf[tn][1] = __float_as_uint(bp[4 * 136]);
        }
#pragma unroll
        for (int tm = 0; tm < 4; tm++)
#pragma unroll
            for (int tn = 0; tn < 4; tn++)
                mma_tf32(acc[tm][tn], a[tm][0], a[tm][1], a[tm][2], a[tm][3],
                         bf[tn][0], bf[tn][1]);
    }

#pragma unroll
    for (int tm = 0; tm < 4; tm++) {
        int r = m0 + wm * 64 + tm * 16 + gid;
#pragma unroll
        for (int tn = 0; tn < 4; tn++) {
            int c = n0 + wn * 32 + tn * 8 + tig * 2;
            float2 v0 = make_float2(acc[tm][tn][0], acc[tm][tn][1]);
            float2 v1 = make_float2(acc[tm][tn][2], acc[tm][tn][3]);
            *(float2*)&out[((size_t)b * LL + r) * DD + c]     = v0;
            *(float2*)&out[((size_t)b * LL + r + 8) * DD + c] = v1;
        }
    }
}

// ---------------------------------------------------------------------------
// Launch
// ---------------------------------------------------------------------------
extern "C" void kernel_launch(void* const* d_in, const int* in_sizes, int n_in,
                              void* d_out, int out_size) {
    (void)in_sizes; (void)n_in; (void)out_size;
    const float* q  = (const float*)d_in[0];
    const float* wr = (const float*)d_in[1];
    const float* wi = (const float*)d_in[2];
    float* out = (float*)d_out;

    static bool attr_done = false;
    if (!attr_done) {
        cudaFuncSetAttribute(fno_stage1_mma,
                             cudaFuncAttributeMaxDynamicSharedMemorySize, S1_SMEM);
        cudaFuncSetAttribute(fno_stage3_mma,
                             cudaFuncAttributeMaxDynamicSharedMemorySize, S3_SMEM);
        attr_done = true;
    }

    fno_init_tables<<<(NK * LL + 255) / 256, 256>>>();
    fno_transpose_w<<<dim3(16, 2, 512), dim3(32, 8)>>>(wr, wi);
    fno_stage1_mma<<<dim3(4, 32), 256, S1_SMEM>>>(q);
    fno_stage2<<<dim3(4, 64), 256>>>();
    fno_stage3_mma<<<dim3(4, 32, 32), 256, S3_SMEM>>>(out);
}

// round 3
// speedup vs baseline: 3.0008x; 1.3481x over previous
#include <cuda_runtime.h>
#include <cuda_bf16.h>
#include <cstdint>

// Problem constants
#define BB 32
#define LL 4096
#define DD 512
#define MODES 64
#define NK 128          // 2*MODES (real rows + imag rows)

// ---------------------------------------------------------------------------
// Static device scratch
// ---------------------------------------------------------------------------
__device__ float g_S1A[NK * LL];                 // [128][4096] rows<64: cos, >=64: -sin (tf32)
__device__ float g_S3A[LL * NK];                 // [4096][128] (tf32)
__device__ float g_Wt[2ull * MODES * DD * DD];   // [ri][m][d][e] (tf32)
__device__ float g_Q[BB * NK * DD];              // [b][row][d] (tf32)
__device__ float g_Am[BB * NK * DD];             // [b][k][e] (tf32)

// ---------------------------------------------------------------------------
// Helpers
// ---------------------------------------------------------------------------
__device__ __forceinline__ uint32_t f2tf(float f) {
    uint32_t u;
    asm("cvt.rna.tf32.f32 %0, %1;" : "=r"(u) : "f"(f));
    return u;
}

__device__ __forceinline__ void mma_tf32(float c[4],
                                         uint32_t a0, uint32_t a1, uint32_t a2, uint32_t a3,
                                         uint32_t b0, uint32_t b1) {
    asm volatile(
        "mma.sync.aligned.m16n8k8.row.col.f32.tf32.tf32.f32 "
        "{%0,%1,%2,%3}, {%4,%5,%6,%7}, {%8,%9}, {%0,%1,%2,%3};"
        : "+f"(c[0]), "+f"(c[1]), "+f"(c[2]), "+f"(c[3])
        : "r"(a0), "r"(a1), "r"(a2), "r"(a3), "r"(b0), "r"(b1));
}

__device__ __forceinline__ void cp16(uint32_t dst_smem, const void* src) {
    asm volatile("cp.async.cg.shared.global [%0], [%1], 16;" :: "r"(dst_smem), "l"(src));
}
__device__ __forceinline__ void cp_commit() { asm volatile("cp.async.commit_group;"); }

// ---------------------------------------------------------------------------
// Init: twiddle tables (tf32-rounded)
// ---------------------------------------------------------------------------
__global__ void fno_init_tables() {
    int idx = blockIdx.x * blockDim.x + threadIdx.x;
    if (idx >= NK * LL) return;
    int row = idx >> 12;
    int l   = idx & (LL - 1);
    int m   = row & (MODES - 1);
    int r   = (m * l) & (LL - 1);
    float s, c;
    sincospif((float)r * (1.0f / 2048.0f), &s, &c);
    float v = (row < MODES) ? c : -s;
    float vt = __uint_as_float(f2tf(v));
    g_S1A[row * LL + l] = vt;
    g_S3A[l * NK + row] = vt;
}

// ---------------------------------------------------------------------------
// Weight transpose: Wt[ri][m][d][e] = tf32(w_ri[d][e][m])
// ---------------------------------------------------------------------------
__global__ void fno_transpose_w(const float* __restrict__ wr,
                                const float* __restrict__ wi) {
    __shared__ float t[2][32][33];
    int d  = blockIdx.z;
    int e0 = blockIdx.x * 32;
    int m0 = blockIdx.y * 32;
    int tx = threadIdx.x, ty = threadIdx.y;
    size_t src_base = ((size_t)d * DD) * MODES + m0;
    for (int i = ty; i < 32; i += 8) {
        t[0][i][tx] = wr[src_base + (size_t)(e0 + i) * MODES + tx];
        t[1][i][tx] = wi[src_base + (size_t)(e0 + i) * MODES + tx];
    }
    __syncthreads();
    for (int i = ty; i < 32; i += 8) {
        size_t dst0 = (((size_t)(m0 + i)) * DD + d) * DD + e0 + tx;
        g_Wt[dst0]                           = __uint_as_float(f2tf(t[0][tx][i]));
        g_Wt[dst0 + (size_t)MODES * DD * DD] = __uint_as_float(f2tf(t[1][tx][i]));
    }
}

// ---------------------------------------------------------------------------
// Stage 1 (tf32 MMA): per-batch C[128,512] = S1A[128,4096] x q_b[4096,512]
// grid (4,32), block 256. BM=128 BN=128 BK=32, warps 2x4, warp tile 64x32.
// Epilogue rounds Q to tf32 so stage2 consumes raw bits.
// ---------------------------------------------------------------------------
#define S1_ASZ (128 * 36)
#define S1_BSZ (32 * 136)
#define S1_BUF (S1_ASZ + S1_BSZ)
#define S1_SMEM (2 * S1_BUF * 4)

__global__ __launch_bounds__(256) void fno_stage1_mma(const float* __restrict__ q) {
    extern __shared__ float sm[];
    const int b  = blockIdx.y;
    const int n0 = blockIdx.x * 128;
    const float* qb = q + (size_t)b * LL * DD;
    const int tid = threadIdx.x;
    const int warp = tid >> 5, lane = tid & 31;
    const int wm = warp >> 2, wn = warp & 3;
    const int gid = lane >> 2, tig = lane & 3;
    const uint32_t smem_u = (uint32_t)__cvta_generic_to_shared(sm);

    float acc[4][4][4];
#pragma unroll
    for (int i = 0; i < 4; i++)
#pragma unroll
        for (int j = 0; j < 4; j++)
#pragma unroll
            for (int k = 0; k < 4; k++) acc[i][j][k] = 0.0f;

    auto load_tiles = [&](int buf, int k0) {
        uint32_t aB = smem_u + buf * S1_BUF * 4;
        uint32_t bB = aB + S1_ASZ * 4;
#pragma unroll
        for (int i = 0; i < 4; i++) {
            int idx = tid + i * 256;
            int row = idx >> 3, c4 = idx & 7;
            cp16(aB + (row * 36 + c4 * 4) * 4, &g_S1A[row * LL + k0 + c4 * 4]);
        }
#pragma unroll
        for (int i = 0; i < 4; i++) {
            int idx = tid + i * 256;
            int kr = idx >> 5, c4 = idx & 31;
            cp16(bB + (kr * 136 + c4 * 4) * 4, &qb[(size_t)(k0 + kr) * DD + n0 + c4 * 4]);
        }
        cp_commit();
    };

    load_tiles(0, 0);
    int buf = 0;
    const int NT = LL / 32;
    for (int kt = 0; kt < NT; kt++) {
        if (kt + 1 < NT) {
            load_tiles(buf ^ 1, (kt + 1) * 32);
            asm volatile("cp.async.wait_group 1;");
        } else {
            asm volatile("cp.async.wait_group 0;");
        }
        __syncthreads();
        const float* As = sm + buf * S1_BUF;
        const float* Bs = As + S1_ASZ;
#pragma unroll
        for (int ks = 0; ks < 4; ks++) {
            uint32_t a[4][4];
#pragma unroll
            for (int tm = 0; tm < 4; tm++) {
                const float* ap = As + (wm * 64 + tm * 16 + gid) * 36 + ks * 8 + tig;
                a[tm][0] = __float_as_uint(ap[0]);
                a[tm][1] = __float_as_uint(ap[8 * 36]);
                a[tm][2] = __float_as_uint(ap[4]);
                a[tm][3] = __float_as_uint(ap[8 * 36 + 4]);
            }
            uint32_t bf[4][2];
#pragma unroll
            for (int tn = 0; tn < 4; tn++) {
                const float* bp = Bs + (ks * 8 + tig) * 136 + wn * 32 + tn * 8 + gid;
                bf[tn][0] = f2tf(bp[0]);
                bf[tn][1] = f2tf(bp[4 * 136]);
            }
#pragma unroll
            for (int tm = 0; tm < 4; tm++)
#pragma unroll
                for (int tn = 0; tn < 4; tn++)
                    mma_tf32(acc[tm][tn], a[tm][0], a[tm][1], a[tm][2], a[tm][3],
                             bf[tn][0], bf[tn][1]);
        }
        __syncthreads();
        buf ^= 1;
    }

#pragma unroll
    for (int tm = 0; tm < 4; tm++) {
        int r = wm * 64 + tm * 16 + gid;
#pragma unroll
        for (int tn = 0; tn < 4; tn++) {
            int c = n0 + wn * 32 + tn * 8 + tig * 2;
            float2 v0 = make_float2(__uint_as_float(f2tf(acc[tm][tn][0])),
                                    __uint_as_float(f2tf(acc[tm][tn][1])));
            float2 v1 = make_float2(__uint_as_float(f2tf(acc[tm][tn][2])),
                                    __uint_as_float(f2tf(acc[tm][tn][3])));
            *(float2*)&g_Q[((size_t)b * NK + r) * DD + c]     = v0;
            *(float2*)&g_Q[((size_t)b * NK + r + 8) * DD + c] = v1;
        }
    }
}

// ---------------------------------------------------------------------------
// Stage 2 (tf32 MMA): per-mode complex GEMM on tensor pipe.
//   Or = Qr*Wr - Qi*Wi ; Oi = Qr*Wi + Qi*Wr   (neg via sign-bit XOR on frag)
// grid (4 e-tiles, 64 modes), block 256 (8 warps: 2 b x 4 e).
// Tile: 32b x 128e, K = 512 d in 32-deep double-buffered chunks.
// ---------------------------------------------------------------------------
#define S2_ASZ (64 * 36)      // [ri*32+b][36]
#define S2_BSZ (64 * 136)     // [ri*32+d][136]
#define S2_BUF (S2_ASZ + S2_BSZ)
#define S2_SMEM (2 * S2_BUF * 4)

__global__ __launch_bounds__(256) void fno_stage2_mma() {
    extern __shared__ float sm[];
    const int m  = blockIdx.y;
    const int e0 = blockIdx.x * 128;
    const int tid = threadIdx.x;
    const int warp = tid >> 5, lane = tid & 31;
    const int wm = warp >> 2;            // 0..1 -> b offset 16*wm
    const int wn = warp & 3;             // 0..3 -> e offset 32*wn
    const int gid = lane >> 2, tig = lane & 3;
    const uint32_t smem_u = (uint32_t)__cvta_generic_to_shared(sm);

    float accR[4][4], accI[4][4];
#pragma unroll
    for (int i = 0; i < 4; i++)
#pragma unroll
        for (int j = 0; j < 4; j++) { accR[i][j] = 0.0f; accI[i][j] = 0.0f; }

    // A rows: ri*32 + b ; source g_Q[(b*NK + ri*MODES + m)*DD + d]
    // B rows: ri*32 + d ; source g_Wt[((ri*MODES + m)*DD + d)*DD + e]
    auto load_tiles = [&](int buf, int d0) {
        uint32_t aB = smem_u + buf * S2_BUF * 4;
        uint32_t bB = aB + S2_ASZ * 4;
        // A: 64 rows x 8 float4  = 512 float4 -> 2 per thread
#pragma unroll
        for (int i = 0; i < 2; i++) {
            int idx = tid + i * 256;
            int row = idx >> 3, c4 = idx & 7;       // row: ri*32+b
            int ri = row >> 5, bb = row & 31;
            cp16(aB + (row * 36 + c4 * 4) * 4,
                 &g_Q[((size_t)bb * NK + ri * MODES + m) * DD + d0 + c4 * 4]);
        }
        // B: 64 rows x 32 float4 = 2048 float4 -> 8 per thread
#pragma unroll
        for (int i = 0; i < 8; i++) {
            int idx = tid + i * 256;
            int row = idx >> 5, c4 = idx & 31;      // row: ri*32+d
            int ri = row >> 5, dr = row & 31;
            cp16(bB + (row * 136 + c4 * 4) * 4,
                 &g_Wt[(((size_t)ri * MODES + m) * DD + d0 + dr) * DD + e0 + c4 * 4]);
        }
        cp_commit();
    };

    load_tiles(0, 0);
    int buf = 0;
    const int NT = DD / 32;     // 16
    for (int kt = 0; kt < NT; kt++) {
        if (kt + 1 < NT) {
            load_tiles(buf ^ 1, (kt + 1) * 32);
            asm volatile("cp.async.wait_group 1;");
        } else {
            asm volatile("cp.async.wait_group 0;");
        }
        __syncthreads();
        const float* As = sm + buf * S2_BUF;
        const float* Bs = As + S2_ASZ;
#pragma unroll
        for (int ks = 0; ks < 4; ks++) {
            // A frags: real (ri=0) and imag (ri=1), m16 tile at rows wm*16..
            uint32_t ar[4], ai[4];
            {
                const float* ap = As + (wm * 16 + gid) * 36 + ks * 8 + tig;
                ar[0] = __float_as_uint(ap[0]);
                ar[1] = __float_as_uint(ap[8 * 36]);
                ar[2] = __float_as_uint(ap[4]);
                ar[3] = __float_as_uint(ap[8 * 36 + 4]);
                const float* aq = ap + 32 * 36;
                ai[0] = __float_as_uint(aq[0]);
                ai[1] = __float_as_uint(aq[8 * 36]);
                ai[2] = __float_as_uint(aq[4]);
                ai[3] = __float_as_uint(aq[8 * 36 + 4]);
            }
#pragma unroll
            for (int tn = 0; tn < 4; tn++) {
                const float* bp = Bs + (ks * 8 + tig) * 136 + wn * 32 + tn * 8 + gid;
                uint32_t br0 = __float_as_uint(bp[0]);
                uint32_t br1 = __float_as_uint(bp[4 * 136]);
                const float* bq = bp + 32 * 136;
                uint32_t bi0 = __float_as_uint(bq[0]);
                uint32_t bi1 = __float_as_uint(bq[4 * 136]);
                mma_tf32(accR[tn], ar[0], ar[1], ar[2], ar[3], br0, br1);
                mma_tf32(accR[tn], ai[0], ai[1], ai[2], ai[3],
                         bi0 ^ 0x80000000u, bi1 ^ 0x80000000u);
                mma_tf32(accI[tn], ar[0], ar[1], ar[2], ar[3], bi0, bi1);
                mma_tf32(accI[tn], ai[0], ai[1], ai[2], ai[3], br0, br1);
            }
        }
        __syncthreads();
        buf ^= 1;
    }

    const float cscale = (m == 0) ? (1.0f / (float)LL) : (2.0f / (float)LL);
#pragma unroll
    for (int tn = 0; tn < 4; tn++) {
        int c = e0 + wn * 32 + tn * 8 + tig * 2;
        int b0r = wm * 16 + gid;
        // real rows -> g_Am row m ; imag rows -> row MODES+m
        float2 r0 = make_float2(__uint_as_float(f2tf(cscale * accR[tn][0])),
                                __uint_as_float(f2tf(cscale * accR[tn][1])));
        float2 r1 = make_float2(__uint_as_float(f2tf(cscale * accR[tn][2])),
                                __uint_as_float(f2tf(cscale * accR[tn][3])));
        float2 i0 = make_float2(__uint_as_float(f2tf(cscale * accI[tn][0])),
                                __uint_as_float(f2tf(cscale * accI[tn][1])));
        float2 i1 = make_float2(__uint_as_float(f2tf(cscale * accI[tn][2])),
                                __uint_as_float(f2tf(cscale * accI[tn][3])));
        *(float2*)&g_Am[((size_t)b0r * NK + m) * DD + c]                = r0;
        *(float2*)&g_Am[((size_t)(b0r + 8) * NK + m) * DD + c]          = r1;
        *(float2*)&g_Am[((size_t)b0r * NK + MODES + m) * DD + c]        = i0;
        *(float2*)&g_Am[((size_t)(b0r + 8) * NK + MODES + m) * DD + c]  = i1;
    }
}

// ---------------------------------------------------------------------------
// Stage 3 (tf32 MMA): out_b[4096,512] = S3A[4096,128] x Am_b[128,512]
// ---------------------------------------------------------------------------
#define S3_ASZ (128 * 132)
#define S3_BSZ (128 * 136)
#define S3_SMEM ((S3_ASZ + S3_BSZ) * 4)

__global__ __launch_bounds__(256) void fno_stage3_mma(float* __restrict__ out) {
    extern __shared__ float sm[];
    const int b  = blockIdx.z;
    const int m0 = blockIdx.y * 128;
    const int n0 = blockIdx.x * 128;
    const int tid = threadIdx.x;
    const int warp = tid >> 5, lane = tid & 31;
    const int wm = warp >> 2, wn = warp & 3;
    const int gid = lane >> 2, tig = lane & 3;
    const uint32_t smem_u = (uint32_t)__cvta_generic_to_shared(sm);
    const float* As = sm;
    const float* Bs = sm + S3_ASZ;

    {
        uint32_t aB = smem_u;
        uint32_t bB = smem_u + S3_ASZ * 4;
#pragma unroll
        for (int i = 0; i < 16; i++) {
            int idx = tid + i * 256;
            int row = idx >> 5, c4 = idx & 31;
            cp16(aB + (row * 132 + c4 * 4) * 4, &g_S3A[(size_t)(m0 + row) * NK + c4 * 4]);
        }
#pragma unroll
        for (int i = 0; i < 16; i++) {
            int idx = tid + i * 256;
            int row = idx >> 5, c4 = idx & 31;
            cp16(bB + (row * 136 + c4 * 4) * 4, &g_Am[((size_t)b * NK + row) * DD + n0 + c4 * 4]);
        }
        cp_commit();
        asm volatile("cp.async.wait_group 0;");
        __syncthreads();
    }

    float acc[4][4][4];
#pragma unroll
    for (int i = 0; i < 4; i++)
#pragma unroll
        for (int j = 0; j < 4; j++)
#pragma unroll
            for (int k = 0; k < 4; k++) acc[i][j][k] = 0.0f;

#pragma unroll 4
    for (int ks = 0; ks < 16; ks++) {
        uint32_t a[4][4];
#pragma unroll
        for (int tm = 0; tm < 4; tm++) {
            const float* ap = As + (wm * 64 + tm * 16 + gid) * 132 + ks * 8 + tig;
            a[tm][0] = __float_as_uint(ap[0]);
            a[tm][1] = __float_as_uint(ap[8 * 132]);
            a[tm][2] = __float_as_uint(ap[4]);
            a[tm][3] = __float_as_uint(ap[8 * 132 + 4]);
        }
        uint32_t bf[4][2];
#pragma unroll
        for (int tn = 0; tn < 4; tn++) {
            const float* bp = Bs + (ks * 8 + tig) * 136 + wn * 32 + tn * 8 + gid;
            bf[tn][0] = __float_as_uint(bp[0]);
            bf[tn][1] = __float_as_uint(bp[4 * 136]);
        }
#pragma unroll
        for (int tm = 0; tm < 4; tm++)
#pragma unroll
            for (int tn = 0; tn < 4; tn++)
                mma_tf32(acc[tm][tn], a[tm][0], a[tm][1], a[tm][2], a[tm][3],
                         bf[tn][0], bf[tn][1]);
    }

#pragma unroll
    for (int tm = 0; tm < 4; tm++) {
        int r = m0 + wm * 64 + tm * 16 + gid;
#pragma unroll
        for (int tn = 0; tn < 4; tn++) {
            int c = n0 + wn * 32 + tn * 8 + tig * 2;
            float2 v0 = make_float2(acc[tm][tn][0], acc[tm][tn][1]);
            float2 v1 = make_float2(acc[tm][tn][2], acc[tm][tn][3]);
            *(float2*)&out[((size_t)b * LL + r) * DD + c]     = v0;
            *(float2*)&out[((size_t)b * LL + r + 8) * DD + c] = v1;
        }
    }
}

// ---------------------------------------------------------------------------
// Launch
// ---------------------------------------------------------------------------
extern "C" void kernel_launch(void* const* d_in, const int* in_sizes, int n_in,
                              void* d_out, int out_size) {
    (void)in_sizes; (void)n_in; (void)out_size;
    const float* q  = (const float*)d_in[0];
    const float* wr = (const float*)d_in[1];
    const float* wi = (const float*)d_in[2];
    float* out = (float*)d_out;

    static bool attr_done = false;
    if (!attr_done) {
        cudaFuncSetAttribute(fno_stage1_mma,
                             cudaFuncAttributeMaxDynamicSharedMemorySize, S1_SMEM);
        cudaFuncSetAttribute(fno_stage2_mma,
                             cudaFuncAttributeMaxDynamicSharedMemorySize, S2_SMEM);
        cudaFuncSetAttribute(fno_stage3_mma,
                             cudaFuncAttributeMaxDynamicSharedMemorySize, S3_SMEM);
        attr_done = true;
    }

    fno_init_tables<<<(NK * LL + 255) / 256, 256>>>();
    fno_transpose_w<<<dim3(16, 2, 512), dim3(32, 8)>>>(wr, wi);
    fno_stage1_mma<<<dim3(4, 32), 256, S1_SMEM>>>(q);
    fno_stage2_mma<<<dim3(4, 64), 256, S2_SMEM>>>();
    fno_stage3_mma<<<dim3(4, 32, 32), 256, S3_SMEM>>>(out);
}

// round 6
// speedup vs baseline: 3.9331x; 1.3107x over previous
#include <cuda_runtime.h>
#include <cuda_bf16.h>
#include <cstdint>

// Problem constants
#define BB 32
#define LL 4096
#define DD 512
#define MODES 64
#define NK 128          // 2*MODES (real rows + imag rows)

// ---------------------------------------------------------------------------
// Static device scratch
// ---------------------------------------------------------------------------
__device__ float g_F1[NK * 2048];                // folded fwd tables [128][2048], l=j+1 (tf32)
__device__ float g_S3A[LL * NK];                 // [4096][128] [l][k]: k<64 cos, k>=64 -sin (tf32)
__device__ float g_Wt[2ull * MODES * DD * DD];   // [ri][m][d][e] (tf32)
__device__ float g_Q[BB * NK * DD];              // [b][row][d] (tf32)
__device__ float g_Am[BB * NK * DD];             // [b][k][e] (tf32)

// ---------------------------------------------------------------------------
// Helpers
// ---------------------------------------------------------------------------
__device__ __forceinline__ uint32_t f2tf(float f) {
    uint32_t u;
    asm("cvt.rna.tf32.f32 %0, %1;" : "=r"(u) : "f"(f));
    return u;
}
__device__ __forceinline__ float f2tf_f(float f) { return __uint_as_float(f2tf(f)); }

__device__ __forceinline__ void mma_tf32(float c[4],
                                         uint32_t a0, uint32_t a1, uint32_t a2, uint32_t a3,
                                         uint32_t b0, uint32_t b1) {
    asm volatile(
        "mma.sync.aligned.m16n8k8.row.col.f32.tf32.tf32.f32 "
        "{%0,%1,%2,%3}, {%4,%5,%6,%7}, {%8,%9}, {%0,%1,%2,%3};"
        : "+f"(c[0]), "+f"(c[1]), "+f"(c[2]), "+f"(c[3])
        : "r"(a0), "r"(a1), "r"(a2), "r"(a3), "r"(b0), "r"(b1));
}

__device__ __forceinline__ void cp16(uint32_t dst_smem, const void* src) {
    asm volatile("cp.async.cg.shared.global [%0], [%1], 16;" :: "r"(dst_smem), "l"(src));
}
__device__ __forceinline__ void cp_commit() { asm volatile("cp.async.commit_group;"); }

// ---------------------------------------------------------------------------
// Init: folded stage-1 tables.  row<64: cos(theta m l), row>=64: -sin ; l=j+1
// ---------------------------------------------------------------------------
__global__ void fno_init_fold() {
    int idx = blockIdx.x * blockDim.x + threadIdx.x;   // 128*2048
    if (idx >= NK * 2048) return;
    int row = idx >> 11;          // 0..127
    int j   = idx & 2047;
    int l   = j + 1;              // 1..2048
    int m   = row & (MODES - 1);
    int r   = (m * l) & (LL - 1);
    float s, c;
    sincospif((float)r * (1.0f / 2048.0f), &s, &c);
    g_F1[row * 2048 + j] = f2tf_f((row < MODES) ? c : -s);
}

// Stage-3 tables (only rows l<2048 used, but fill all for simplicity)
__global__ void fno_init_tables() {
    int idx = blockIdx.x * blockDim.x + threadIdx.x;
    if (idx >= NK * LL) return;
    int row = idx >> 12;
    int l   = idx & (LL - 1);
    int m   = row & (MODES - 1);
    int r   = (m * l) & (LL - 1);
    float s, c;
    sincospif((float)r * (1.0f / 2048.0f), &s, &c);
    g_S3A[l * NK + row] = f2tf_f((row < MODES) ? c : -s);
}

// ---------------------------------------------------------------------------
// Weight transpose: Wt[ri][m][d][e] = tf32(w_ri[d][e][m])
// ---------------------------------------------------------------------------
__global__ void fno_transpose_w(const float* __restrict__ wr,
                                const float* __restrict__ wi) {
    __shared__ float t[2][32][33];
    int d  = blockIdx.z;
    int e0 = blockIdx.x * 32;
    int m0 = blockIdx.y * 32;
    int tx = threadIdx.x, ty = threadIdx.y;
    size_t src_base = ((size_t)d * DD) * MODES + m0;
    for (int i = ty; i < 32; i += 8) {
        t[0][i][tx] = wr[src_base + (size_t)(e0 + i) * MODES + tx];
        t[1][i][tx] = wi[src_base + (size_t)(e0 + i) * MODES + tx];
    }
    __syncthreads();
    for (int i = ty; i < 32; i += 8) {
        size_t dst0 = (((size_t)(m0 + i)) * DD + d) * DD + e0 + tx;
        g_Wt[dst0]                           = f2tf_f(t[0][tx][i]);
        g_Wt[dst0 + (size_t)MODES * DD * DD] = f2tf_f(t[1][tx][i]);
    }
}

// ===========================================================================
// Stage 1 (folded, tf32 MMA): per-batch
//   Qr[64,512] = cosF[64,2048] x P[2048,512]   (+ q[0,:] correction)
//   Qi[64,512] = (-sinF)[64,2048] x D[2048,512]
// where P[l]=q[l]+q[4096-l], D[l]=q[l]-q[4096-l] (l=2048 partner zeroed).
// grid (4 n-tiles, 32 b), block 256 (8 warps: wm in {0=Qr,1=Qi}, wn 0..3).
// Warp tile 64x32. K chunks of 32, A double-buffered cp.async, B via
// register-pipelined LDG -> fold -> STS (double-buffered P/D tiles).
// ===========================================================================
#define F1_A_F (128 * 36)
#define F1_B_F (32 * 136)
// layout: A[2], then per-buf {P,D}[2]
#define S1F_SMEM ((2 * F1_A_F + 4 * F1_B_F) * 4)

__global__ __launch_bounds__(256) void fno_stage1_fold(const float* __restrict__ q) {
    extern __shared__ float sm[];
    float* Bbase = sm + 2 * F1_A_F;
    const int b  = blockIdx.y;
    const int n0 = blockIdx.x * 128;
    const float* qb = q + (size_t)b * LL * DD;
    const int tid = threadIdx.x;
    const int warp = tid >> 5, lane = tid & 31;
    const int wm = warp >> 2, wn = warp & 3;
    const int gid = lane >> 2, tig = lane & 3;
    const uint32_t smu = (uint32_t)__cvta_generic_to_shared(sm);

    float acc[4][4][4];
#pragma unroll
    for (int i = 0; i < 4; i++)
#pragma unroll
        for (int j = 0; j < 4; j++)
#pragma unroll
            for (int k = 0; k < 4; k++) acc[i][j][k] = 0.0f;

    // per-thread B-load jobs: 4 x (row j, col c4)
    float4 v1[4], v2[4];
    auto ldB = [&](int k0) {
#pragma unroll
        for (int i = 0; i < 4; i++) {
            int idx = tid + i * 256;
            int j = idx >> 5, c4 = idx & 31;
            int l = k0 + j + 1;
            v1[i] = *(const float4*)&qb[(size_t)l * DD + n0 + c4 * 4];
            if (l == 2048) {
                v2[i] = make_float4(0.f, 0.f, 0.f, 0.f);
            } else {
                v2[i] = *(const float4*)&qb[(size_t)(LL - l) * DD + n0 + c4 * 4];
            }
        }
    };
    auto stB = [&](int buf) {
        float* P = Bbase + buf * 2 * F1_B_F;
        float* Dn = P + F1_B_F;
#pragma unroll
        for (int i = 0; i < 4; i++) {
            int idx = tid + i * 256;
            int j = idx >> 5, c4 = idx & 31;
            float4 p, d;
            p.x = f2tf_f(v1[i].x + v2[i].x);  d.x = f2tf_f(v1[i].x - v2[i].x);
            p.y = f2tf_f(v1[i].y + v2[i].y);  d.y = f2tf_f(v1[i].y - v2[i].y);
            p.z = f2tf_f(v1[i].z + v2[i].z);  d.z = f2tf_f(v1[i].z - v2[i].z);
            p.w = f2tf_f(v1[i].w + v2[i].w);  d.w = f2tf_f(v1[i].w - v2[i].w);
            *(float4*)&P[j * 136 + c4 * 4]  = p;
            *(float4*)&Dn[j * 136 + c4 * 4] = d;
        }
    };
    auto cpA = [&](int buf, int k0) {
        uint32_t aB = smu + buf * F1_A_F * 4;
#pragma unroll
        for (int i = 0; i < 4; i++) {
            int idx = tid + i * 256;
            int row = idx >> 3, c4 = idx & 7;
            cp16(aB + (row * 36 + c4 * 4) * 4, &g_F1[row * 2048 + k0 + c4 * 4]);
        }
        cp_commit();
    };

    cpA(0, 0);
    ldB(0);
    const int NT = 64;          // 2048 / 32
    for (int kt = 0; kt < NT; kt++) {
        int buf = kt & 1;
        stB(buf);
        if (kt + 1 < NT) {
            cpA(buf ^ 1, (kt + 1) * 32);
            asm volatile("cp.async.wait_group 1;");
        } else {
            asm volatile("cp.async.wait_group 0;");
        }
        __syncthreads();
        if (kt + 1 < NT) ldB((kt + 1) * 32);

        const float* As = sm + buf * F1_A_F;
        const float* Bs = Bbase + buf * 2 * F1_B_F + wm * F1_B_F;  // P or D
#pragma unroll
        for (int ks = 0; ks < 4; ks++) {
            uint32_t a[4][4];
#pragma unroll
            for (int tm = 0; tm < 4; tm++) {
                const float* ap = As + (wm * 64 + tm * 16 + gid) * 36 + ks * 8 + tig;
                a[tm][0] = __float_as_uint(ap[0]);
                a[tm][1] = __float_as_uint(ap[8 * 36]);
                a[tm][2] = __float_as_uint(ap[4]);
                a[tm][3] = __float_as_uint(ap[8 * 36 + 4]);
            }
            uint32_t bf[4][2];
#pragma unroll
            for (int tn = 0; tn < 4; tn++) {
                const float* bp = Bs + (ks * 8 + tig) * 136 + wn * 32 + tn * 8 + gid;
                bf[tn][0] = __float_as_uint(bp[0]);
                bf[tn][1] = __float_as_uint(bp[4 * 136]);
            }
#pragma unroll
            for (int tm = 0; tm < 4; tm++)
#pragma unroll
                for (int tn = 0; tn < 4; tn++)
                    mma_tf32(acc[tm][tn], a[tm][0], a[tm][1], a[tm][2], a[tm][3],
                             bf[tn][0], bf[tn][1]);
        }
        __syncthreads();
    }

    // epilogue: Qr rows (wm=0) need the l=0 term: += q[0][c]
#pragma unroll
    for (int tm = 0; tm < 4; tm++) {
        int r = wm * 64 + tm * 16 + gid;     // global row in [0,128)
#pragma unroll
        for (int tn = 0; tn < 4; tn++) {
            int c = n0 + wn * 32 + tn * 8 + tig * 2;
            float c0 = 0.f, c1 = 0.f;
            if (wm == 0) { c0 = qb[c]; c1 = qb[c + 1]; }
            float2 v0 = make_float2(f2tf_f(acc[tm][tn][0] + c0),
                                    f2tf_f(acc[tm][tn][1] + c1));
            float2 v1s = make_float2(f2tf_f(acc[tm][tn][2] + c0),
                                     f2tf_f(acc[tm][tn][3] + c1));
            *(float2*)&g_Q[((size_t)b * NK + r) * DD + c]     = v0;
            *(float2*)&g_Q[((size_t)b * NK + r + 8) * DD + c] = v1s;
        }
    }
}

// ---------------------------------------------------------------------------
// Stage 2 (tf32 mma.sync, unchanged from R3): per-mode complex GEMM.
// ---------------------------------------------------------------------------
#define S2_ASZ (64 * 36)
#define S2_BSZ (64 * 136)
#define S2_BUF (S2_ASZ + S2_BSZ)
#define S2_SMEM (2 * S2_BUF * 4)

__global__ __launch_bounds__(256) void fno_stage2_mma() {
    extern __shared__ float sm[];
    const int m  = blockIdx.y;
    const int e0 = blockIdx.x * 128;
    const int tid = threadIdx.x;
    const int warp = tid >> 5, lane = tid & 31;
    const int wm = warp >> 2;
    const int wn = warp & 3;
    const int gid = lane >> 2, tig = lane & 3;
    const uint32_t smem_u = (uint32_t)__cvta_generic_to_shared(sm);

    float accR[4][4], accI[4][4];
#pragma unroll
    for (int i = 0; i < 4; i++)
#pragma unroll
        for (int j = 0; j < 4; j++) { accR[i][j] = 0.0f; accI[i][j] = 0.0f; }

    auto load_tiles = [&](int buf, int d0) {
        uint32_t aB = smem_u + buf * S2_BUF * 4;
        uint32_t bB = aB + S2_ASZ * 4;
#pragma unroll
        for (int i = 0; i < 2; i++) {
            int idx = tid + i * 256;
            int row = idx >> 3, c4 = idx & 7;
            int ri = row >> 5, bb = row & 31;
            cp16(aB + (row * 36 + c4 * 4) * 4,
                 &g_Q[((size_t)bb * NK + ri * MODES + m) * DD + d0 + c4 * 4]);
        }
#pragma unroll
        for (int i = 0; i < 8; i++) {
            int idx = tid + i * 256;
            int row = idx >> 5, c4 = idx & 31;
            int ri = row >> 5, dr = row & 31;
            cp16(bB + (row * 136 + c4 * 4) * 4,
                 &g_Wt[(((size_t)ri * MODES + m) * DD + d0 + dr) * DD + e0 + c4 * 4]);
        }
        cp_commit();
    };

    load_tiles(0, 0);
    int buf = 0;
    const int NT = DD / 32;
    for (int kt = 0; kt < NT; kt++) {
        if (kt + 1 < NT) {
            load_tiles(buf ^ 1, (kt + 1) * 32);
            asm volatile("cp.async.wait_group 1;");
        } else {
            asm volatile("cp.async.wait_group 0;");
        }
        __syncthreads();
        const float* As = sm + buf * S2_BUF;
        const float* Bs = As + S2_ASZ;
#pragma unroll
        for (int ks = 0; ks < 4; ks++) {
            uint32_t ar[4], ai[4];
            {
                const float* ap = As + (wm * 16 + gid) * 36 + ks * 8 + tig;
                ar[0] = __float_as_uint(ap[0]);
                ar[1] = __float_as_uint(ap[8 * 36]);
                ar[2] = __float_as_uint(ap[4]);
                ar[3] = __float_as_uint(ap[8 * 36 + 4]);
                const float* aq = ap + 32 * 36;
                ai[0] = __float_as_uint(aq[0]);
                ai[1] = __float_as_uint(aq[8 * 36]);
                ai[2] = __float_as_uint(aq[4]);
                ai[3] = __float_as_uint(aq[8 * 36 + 4]);
            }
#pragma unroll
            for (int tn = 0; tn < 4; tn++) {
                const float* bp = Bs + (ks * 8 + tig) * 136 + wn * 32 + tn * 8 + gid;
                uint32_t br0 = __float_as_uint(bp[0]);
                uint32_t br1 = __float_as_uint(bp[4 * 136]);
                const float* bq = bp + 32 * 136;
                uint32_t bi0 = __float_as_uint(bq[0]);
                uint32_t bi1 = __float_as_uint(bq[4 * 136]);
                mma_tf32(accR[tn], ar[0], ar[1], ar[2], ar[3], br0, br1);
                mma_tf32(accR[tn], ai[0], ai[1], ai[2], ai[3],
                         bi0 ^ 0x80000000u, bi1 ^ 0x80000000u);
                mma_tf32(accI[tn], ar[0], ar[1], ar[2], ar[3], bi0, bi1);
                mma_tf32(accI[tn], ai[0], ai[1], ai[2], ai[3], br0, br1);
            }
        }
        __syncthreads();
        buf ^= 1;
    }

    const float cscale = (m == 0) ? (1.0f / (float)LL) : (2.0f / (float)LL);
#pragma unroll
    for (int tn = 0; tn < 4; tn++) {
        int c = e0 + wn * 32 + tn * 8 + tig * 2;
        int b0r = wm * 16 + gid;
        float2 r0 = make_float2(f2tf_f(cscale * accR[tn][0]), f2tf_f(cscale * accR[tn][1]));
        float2 r1 = make_float2(f2tf_f(cscale * accR[tn][2]), f2tf_f(cscale * accR[tn][3]));
        float2 i0 = make_float2(f2tf_f(cscale * accI[tn][0]), f2tf_f(cscale * accI[tn][1]));
        float2 i1 = make_float2(f2tf_f(cscale * accI[tn][2]), f2tf_f(cscale * accI[tn][3]));
        *(float2*)&g_Am[((size_t)b0r * NK + m) * DD + c]               = r0;
        *(float2*)&g_Am[((size_t)(b0r + 8) * NK + m) * DD + c]         = r1;
        *(float2*)&g_Am[((size_t)b0r * NK + MODES + m) * DD + c]       = i0;
        *(float2*)&g_Am[((size_t)(b0r + 8) * NK + MODES + m) * DD + c] = i1;
    }
}

// ===========================================================================
// Stage 3 (folded, tf32 MMA): for l in [0,2048):
//   C[l] = sum_{k<64}  cos * Amr ;  S[l] = sum_{k>=64} (-sin) * Ami
//   out[l] = C+S ; out[4096-l] = C-S (skip l==0)
// grid (4 n-tiles, 16 l-tiles, 32 b), block 256. BM=128 BN=128 K=128 split.
// ===========================================================================
#define S3_ASZ (128 * 132)
#define S3_BSZ (128 * 136)
#define S3_SMEM ((S3_ASZ + S3_BSZ) * 4)

__global__ __launch_bounds__(256) void fno_stage3_fold(float* __restrict__ out) {
    extern __shared__ float sm[];
    const int b  = blockIdx.z;
    const int l0 = blockIdx.y * 128;
    const int n0 = blockIdx.x * 128;
    const int tid = threadIdx.x;
    const int warp = tid >> 5, lane = tid & 31;
    const int wm = warp >> 2, wn = warp & 3;
    const int gid = lane >> 2, tig = lane & 3;
    const uint32_t smem_u = (uint32_t)__cvta_generic_to_shared(sm);
    const float* As = sm;
    const float* Bs = sm + S3_ASZ;

    {
        uint32_t aB = smem_u;
        uint32_t bB = smem_u + S3_ASZ * 4;
#pragma unroll
        for (int i = 0; i < 16; i++) {
            int idx = tid + i * 256;
            int row = idx >> 5, c4 = idx & 31;
            cp16(aB + (row * 132 + c4 * 4) * 4, &g_S3A[(size_t)(l0 + row) * NK + c4 * 4]);
        }
#pragma unroll
        for (int i = 0; i < 16; i++) {
            int idx = tid + i * 256;
            int row = idx >> 5, c4 = idx & 31;
            cp16(bB + (row * 136 + c4 * 4) * 4, &g_Am[((size_t)b * NK + row) * DD + n0 + c4 * 4]);
        }
        cp_commit();
        asm volatile("cp.async.wait_group 0;");
        __syncthreads();
    }

    float accC[4][4][4], accS[4][4][4];
#pragma unroll
    for (int i = 0; i < 4; i++)
#pragma unroll
        for (int j = 0; j < 4; j++)
#pragma unroll
            for (int k = 0; k < 4; k++) { accC[i][j][k] = 0.0f; accS[i][j][k] = 0.0f; }

#pragma unroll 4
    for (int ks = 0; ks < 16; ks++) {
        uint32_t a[4][4];
#pragma unroll
        for (int tm = 0; tm < 4; tm++) {
            const float* ap = As + (wm * 64 + tm * 16 + gid) * 132 + ks * 8 + tig;
            a[tm][0] = __float_as_uint(ap[0]);
            a[tm][1] = __float_as_uint(ap[8 * 132]);
            a[tm][2] = __float_as_uint(ap[4]);
            a[tm][3] = __float_as_uint(ap[8 * 132 + 4]);
        }
        uint32_t bf[4][2];
#pragma unroll
        for (int tn = 0; tn < 4; tn++) {
            const float* bp = Bs + (ks * 8 + tig) * 136 + wn * 32 + tn * 8 + gid;
            bf[tn][0] = __float_as_uint(bp[0]);
            bf[tn][1] = __float_as_uint(bp[4 * 136]);
        }
        if (ks < 8) {
#pragma unroll
            for (int tm = 0; tm < 4; tm++)
#pragma unroll
                for (int tn = 0; tn < 4; tn++)
                    mma_tf32(accC[tm][tn], a[tm][0], a[tm][1], a[tm][2], a[tm][3],
                             bf[tn][0], bf[tn][1]);
        } else {
#pragma unroll
            for (int tm = 0; tm < 4; tm++)
#pragma unroll
                for (int tn = 0; tn < 4; tn++)
                    mma_tf32(accS[tm][tn], a[tm][0], a[tm][1], a[tm][2], a[tm][3],
                             bf[tn][0], bf[tn][1]);
        }
    }

#pragma unroll
    for (int tm = 0; tm < 4; tm++) {
        int lA = l0 + wm * 64 + tm * 16 + gid;       // row for acc[0..1]
        int lB = lA + 8;                              // row for acc[2..3]
#pragma unroll
        for (int tn = 0; tn < 4; tn++) {
            int c = n0 + wn * 32 + tn * 8 + tig * 2;
            float C0 = accC[tm][tn][0], C1 = accC[tm][tn][1];
            float C2 = accC[tm][tn][2], C3 = accC[tm][tn][3];
            float S0 = accS[tm][tn][0], S1 = accS[tm][tn][1];
            float S2 = accS[tm][tn][2], S3 = accS[tm][tn][3];
            *(float2*)&out[((size_t)b * LL + lA) * DD + c] = make_float2(C0 + S0, C1 + S1);
            *(float2*)&out[((size_t)b * LL + lB) * DD + c] = make_float2(C2 + S2, C3 + S3);
            if (lA > 0)
                *(float2*)&out[((size_t)b * LL + (LL - lA)) * DD + c] =
                    make_float2(C0 - S0, C1 - S1);
            *(float2*)&out[((size_t)b * LL + (LL - lB)) * DD + c] =
                make_float2(C2 - S2, C3 - S3);
        }
    }
}

// ---------------------------------------------------------------------------
// Row l=2048:  out[b,2048,e] = sum_m (-1)^m * Amr[b,m,e]
// ---------------------------------------------------------------------------
__global__ void fno_row2048(float* __restrict__ out) {
    int b = blockIdx.y;
    int e = blockIdx.x * 128 + threadIdx.x;
    float s = 0.0f;
#pragma unroll
    for (int m = 0; m < MODES; m++) {
        float v = g_Am[((size_t)b * NK + m) * DD + e];
        s += (m & 1) ? -v : v;
    }
    out[((size_t)b * LL + 2048) * DD + e] = s;
}

// ---------------------------------------------------------------------------
// Launch
// ---------------------------------------------------------------------------
extern "C" void kernel_launch(void* const* d_in, const int* in_sizes, int n_in,
                              void* d_out, int out_size) {
    (void)in_sizes; (void)n_in; (void)out_size;
    const float* q  = (const float*)d_in[0];
    const float* wr = (const float*)d_in[1];
    const float* wi = (const float*)d_in[2];
    float* out = (float*)d_out;

    static bool attr_done = false;
    if (!attr_done) {
        cudaFuncSetAttribute(fno_stage1_fold,
                             cudaFuncAttributeMaxDynamicSharedMemorySize, S1F_SMEM);
        cudaFuncSetAttribute(fno_stage2_mma,
                             cudaFuncAttributeMaxDynamicSharedMemorySize, S2_SMEM);
        cudaFuncSetAttribute(fno_stage3_fold,
                             cudaFuncAttributeMaxDynamicSharedMemorySize, S3_SMEM);
        attr_done = true;
    }

    fno_init_fold<<<(NK * 2048 + 255) / 256, 256>>>();
    fno_init_tables<<<(NK * LL + 255) / 256, 256>>>();
    fno_transpose_w<<<dim3(16, 2, 512), dim3(32, 8)>>>(wr, wi);
    fno_stage1_fold<<<dim3(4, 32), 256, S1F_SMEM>>>(q);
    fno_stage2_mma<<<dim3(4, 64), 256, S2_SMEM>>>();
    fno_stage3_fold<<<dim3(4, 16, 32), 256, S3_SMEM>>>(out);
    fno_row2048<<<dim3(4, 32), 128>>>(out);
}